// round 2
// baseline (speedup 1.0000x reference)
#include <cuda_runtime.h>
#include <math.h>

#define B 32
#define C 128
#define L 4096
#define NROW (B*C)
#define BCL (B*C*L)            // 16777216
#define FL 9
#define DIM 512
#define NYL ((size_t)BCL)

// ---------------- scratch (device globals; no allocation) ----------------
__device__ float g_a1[BCL];
__device__ float g_a2[BCL];
__device__ float g_a3[BCL];
__device__ float g_attn[B*(C/4)*L];
__device__ float g_feat[B*C];
__device__ float g_wt[3*C*3*C];      // [lvl][ci][k][co]

__device__ __forceinline__ float gelu_f(float x){
    return 0.5f*x*(1.0f+erff(x*0.7071067811865476f));
}
__device__ __forceinline__ float sigmoid_f(float x){
    return 1.0f/(1.0f+expf(-x));
}

// ---------------- mean over L ----------------
__global__ __launch_bounds__(256) void mean_kernel(const float* __restrict__ x,
                                                   float* __restrict__ feat){
    int row = blockIdx.x;
    const float4* p = (const float4*)(x + (size_t)row*L);
    float s = 0.f;
    for (int i = threadIdx.x; i < L/4; i += 256){
        float4 v = p[i];
        s += (v.x+v.y)+(v.z+v.w);
    }
    __shared__ float red[256];
    red[threadIdx.x] = s; __syncthreads();
    for (int off = 128; off > 0; off >>= 1){
        if (threadIdx.x < off) red[threadIdx.x] += red[threadIdx.x+off];
        __syncthreads();
    }
    if (threadIdx.x == 0) feat[row] = red[0] * (1.0f/(float)L);
}

// ---------------- fused MLP: feat->512->1024->18, write lo/hi ----------------
__global__ __launch_bounds__(512) void mlp_kernel(
    const float* __restrict__ feat,
    const float* __restrict__ stat_w, const float* __restrict__ stat_b,
    const float* __restrict__ wg1_w,  const float* __restrict__ wg1_b,
    const float* __restrict__ wg2_w,  const float* __restrict__ wg2_b,
    float* __restrict__ lo_out, float* __restrict__ hi_out)
{
    __shared__ float s_feat[C];
    __shared__ float s_h1[DIM];
    __shared__ float s_h2[2*DIM];
    int b = blockIdx.x, t = threadIdx.x;
    if (t < C) s_feat[t] = feat[b*C + t];
    __syncthreads();
    // layer 1: 512 outputs, K=128
    {
        float acc = stat_b[t];
        const float* wr = stat_w + (size_t)t*C;
        #pragma unroll 8
        for (int c = 0; c < C; c++) acc += wr[c]*s_feat[c];
        s_h1[t] = gelu_f(acc);
    }
    __syncthreads();
    // layer 2: 1024 outputs, K=512
    #pragma unroll
    for (int rep = 0; rep < 2; rep++){
        int j = t + rep*DIM;
        float acc = wg1_b[j];
        const float* wr = wg1_w + (size_t)j*DIM;
        #pragma unroll 8
        for (int c = 0; c < DIM; c++) acc += wr[c]*s_h1[c];
        s_h2[j] = gelu_f(acc);
    }
    __syncthreads();
    // layer 3: 18 outputs, K=1024
    if (t < 2*FL){
        float acc = wg2_b[t];
        const float* wr = wg2_w + (size_t)t*(2*DIM);
        #pragma unroll 8
        for (int c = 0; c < 2*DIM; c++) acc += wr[c]*s_h2[c];
        if (t < FL) lo_out[b*FL + t]        = acc;
        else        hi_out[b*FL + (t-FL)]   = acc;
    }
}

// ---------------- ortho loss (last level only) + energy=0 ----------------
__global__ void ortho_kernel(const float* __restrict__ lo, float* __restrict__ out_scalars){
    int b = threadIdx.x;  // 32 threads
    float v[FL]; float ss = 0.f;
    #pragma unroll
    for (int k = 0; k < FL; k++){ v[k] = lo[b*FL+k]; ss += v[k]*v[k]; }
    float den = sqrtf(ss) + 1e-8f;
    float S = 0.f, sq = 0.f;
    #pragma unroll
    for (int k = 0; k < FL; k++){
        float n = v[k]/den;
        S  += fabsf(n);
        sq += n*n;
    }
    float S2  = S*S;
    float amp = fabsf(sq - 1.0f);
    float sm  = fabsf(v[0]);
    #pragma unroll
    for (int k = 1; k < FL; k++) sm += fabsf(v[k]-v[k-1]);
    sm += fabsf(v[FL-1]);
    #pragma unroll
    for (int off = 16; off > 0; off >>= 1){
        S2  += __shfl_xor_sync(0xffffffffu, S2,  off);
        amp += __shfl_xor_sync(0xffffffffu, amp, off);
        sm  += __shfl_xor_sync(0xffffffffu, sm,  off);
    }
    if (b == 0){
        float shift  = 3.0f * S2 / (32.0f*81.0f);
        float ampm   = amp / 32.0f;
        float smm    = sm / (32.0f*10.0f);
        out_scalars[0] = 0.01f*(shift + ampm) + 0.1f*smm;  // ortho_loss
        out_scalars[1] = 0.0f;                              // energy_loss
    }
}

// ---------------- per-sample depthwise 9-tap (edge pad), lo+hi fused ----------------
#define DTL 1024
__global__ __launch_bounds__(256) void dw_kernel(
    const float* __restrict__ x, const float* __restrict__ lo, const float* __restrict__ hi,
    float* __restrict__ out_a, float* __restrict__ out_d)
{
    int row = blockIdx.y;          // b*C + c
    int b   = row >> 7;
    int l0  = blockIdx.x * DTL;
    __shared__ float s[DTL + 8];
    const float* xr = x + (size_t)row * L;
    for (int i = threadIdx.x; i < DTL + 8; i += 256){
        int li = l0 + i - 4;
        li = min(max(li, 0), L-1);
        s[i] = xr[li];
    }
    float flt[FL], fht[FL];
    #pragma unroll
    for (int k = 0; k < FL; k++){ flt[k] = __ldg(&lo[b*FL+k]); fht[k] = __ldg(&hi[b*FL+k]); }
    __syncthreads();
    for (int i = threadIdx.x; i < DTL; i += 256){
        float a = 0.f, d = 0.f;
        #pragma unroll
        for (int k = 0; k < FL; k++){
            float v = s[i+k];
            a += flt[k]*v;
            d += fht[k]*v;
        }
        size_t idx = (size_t)row*L + l0 + i;
        out_a[idx] = a;
        out_d[idx] = d;
    }
}

// ---------------- transpose gates weights: [lvl][co][ci][k] -> [lvl][ci][k][co] ----------------
__global__ void transpose_w_kernel(const float* __restrict__ gw, float* __restrict__ wt){
    int idx = blockIdx.x*256 + threadIdx.x;
    if (idx < 3*C*C*3){
        int lvl = idx / (C*C*3);
        int r   = idx % (C*C*3);
        int ci  = r / (3*C);
        int k   = (r % (3*C)) / C;
        int co  = r % C;
        wt[idx] = gw[(size_t)lvl*C*C*3 + ((size_t)co*C + ci)*3 + k];
    }
}

// ---------------- gates conv: out = cur + sigmoid(conv3(cur)) * det ----------------
// grid (L/64, B), 256 threads; warp w -> co[16w..16w+15], lane -> l in {lane, lane+32}
__global__ __launch_bounds__(256) void gates_kernel(
    const float* __restrict__ cur, const float* __restrict__ det,
    const float* __restrict__ wt /* [ci][k][co] */, const float* __restrict__ bias,
    float* __restrict__ out)
{
    __shared__ float s_x[C*66];       // [ci][j], window l0-1 .. l0+64
    __shared__ float s_w[8*3*C];      // ci chunk of 8
    int l0 = blockIdx.x*64, b = blockIdx.y, t = threadIdx.x;
    for (int idx = t; idx < C*66; idx += 256){
        int ci = idx/66, j = idx%66;
        int li = l0 + j - 1;
        float v = 0.f;
        if (li >= 0 && li < L) v = cur[((size_t)(b*C+ci))*L + li];
        s_x[idx] = v;
    }
    int wid = t >> 5, lane = t & 31, co0 = wid*16;
    float acc[16][2];
    #pragma unroll
    for (int c = 0; c < 16; c++){ acc[c][0] = 0.f; acc[c][1] = 0.f; }

    for (int ci0 = 0; ci0 < C; ci0 += 8){
        __syncthreads();
        for (int idx = t; idx < 8*3*C; idx += 256) s_w[idx] = wt[ci0*3*C + idx];
        __syncthreads();
        #pragma unroll
        for (int ci = 0; ci < 8; ci++){
            #pragma unroll
            for (int k = 0; k < 3; k++){
                const float4* wp = (const float4*)(&s_w[(ci*3+k)*C + co0]);
                float wr[16];
                ((float4*)wr)[0] = wp[0];
                ((float4*)wr)[1] = wp[1];
                ((float4*)wr)[2] = wp[2];
                ((float4*)wr)[3] = wp[3];
                float x0 = s_x[(ci0+ci)*66 + lane + k];
                float x1 = s_x[(ci0+ci)*66 + lane + 32 + k];
                #pragma unroll
                for (int c = 0; c < 16; c++){
                    acc[c][0] += wr[c]*x0;
                    acc[c][1] += wr[c]*x1;
                }
            }
        }
    }
    #pragma unroll
    for (int c = 0; c < 16; c++){
        int co = co0 + c;
        float bv = bias[co];
        #pragma unroll
        for (int j = 0; j < 2; j++){
            size_t idx = ((size_t)(b*C+co))*L + l0 + lane + j*32;
            float g = sigmoid_f(acc[c][j] + bv);
            out[idx] = cur[idx] + g*det[idx];
        }
    }
}

// ---------------- attn1: 1x1 conv 128->32 + gelu ----------------
// grid (L/128, B), 256 threads; warp w -> co[4w..4w+3], lane -> l in lane+{0,32,64,96}
__global__ __launch_bounds__(256) void attn1_kernel(
    const float* __restrict__ cur, const float* __restrict__ w /* (32,128) */,
    const float* __restrict__ bias, float* __restrict__ outa)
{
    __shared__ float s_x[32*128];     // ci chunk of 32
    __shared__ float s_w[128*33];     // [ci][co] padded
    int b = blockIdx.y, l0 = blockIdx.x*128, t = threadIdx.x;
    for (int idx = t; idx < 32*C; idx += 256){
        int co = idx >> 7, ci = idx & 127;
        s_w[ci*33 + co] = w[idx];
    }
    int wid = t >> 5, lane = t & 31, co0 = wid*4;
    float acc[4][4];
    #pragma unroll
    for (int c = 0; c < 4; c++)
        #pragma unroll
        for (int j = 0; j < 4; j++) acc[c][j] = 0.f;

    for (int ci0 = 0; ci0 < C; ci0 += 32){
        __syncthreads();
        for (int idx = t; idx < 32*128; idx += 256){
            int ci = idx >> 7, l = idx & 127;
            s_x[idx] = cur[((size_t)(b*C + ci0 + ci))*L + l0 + l];
        }
        __syncthreads();
        #pragma unroll 4
        for (int ci = 0; ci < 32; ci++){
            float xv[4];
            #pragma unroll
            for (int j = 0; j < 4; j++) xv[j] = s_x[ci*128 + lane + j*32];
            #pragma unroll
            for (int c = 0; c < 4; c++){
                float wv = s_w[(ci0+ci)*33 + co0 + c];
                #pragma unroll
                for (int j = 0; j < 4; j++) acc[c][j] += wv*xv[j];
            }
        }
    }
    #pragma unroll
    for (int c = 0; c < 4; c++){
        float bv = bias[co0+c];
        #pragma unroll
        for (int j = 0; j < 4; j++){
            size_t idx = ((size_t)(b*32 + co0 + c))*L + l0 + lane + j*32;
            outa[idx] = gelu_f(acc[c][j] + bv);
        }
    }
}

// ---------------- attn2: 1x1 conv 32->128 + sigmoid; det *= (1+attn) in place ----------------
// grid (L/128, B), 256 threads; warp w -> co[16w..16w+15], lane -> l in lane+{0,32,64,96}
__global__ __launch_bounds__(256) void attn2_kernel(
    const float* __restrict__ a, const float* __restrict__ w /* (128,32) */,
    const float* __restrict__ bias, float* __restrict__ det)
{
    __shared__ float s_x[32*128];
    __shared__ float s_w[32*132];     // [ci][co] padded stride 132
    int b = blockIdx.y, l0 = blockIdx.x*128, t = threadIdx.x;
    for (int idx = t; idx < 32*128; idx += 256){
        int ci = idx >> 7, l = idx & 127;
        s_x[idx] = a[((size_t)(b*32 + ci))*L + l0 + l];
    }
    for (int idx = t; idx < C*32; idx += 256){
        int co = idx >> 5, ci = idx & 31;
        s_w[ci*132 + co] = w[idx];
    }
    __syncthreads();
    int wid = t >> 5, lane = t & 31, co0 = wid*16;
    float acc[16][4];
    #pragma unroll
    for (int c = 0; c < 16; c++)
        #pragma unroll
        for (int j = 0; j < 4; j++) acc[c][j] = 0.f;
    #pragma unroll 4
    for (int ci = 0; ci < 32; ci++){
        float wr[16];
        const float4* wp = (const float4*)(&s_w[ci*132 + co0]);
        ((float4*)wr)[0] = wp[0];
        ((float4*)wr)[1] = wp[1];
        ((float4*)wr)[2] = wp[2];
        ((float4*)wr)[3] = wp[3];
        float xv[4];
        #pragma unroll
        for (int j = 0; j < 4; j++) xv[j] = s_x[ci*128 + lane + j*32];
        #pragma unroll
        for (int c = 0; c < 16; c++)
            #pragma unroll
            for (int j = 0; j < 4; j++) acc[c][j] += wr[c]*xv[j];
    }
    #pragma unroll
    for (int c = 0; c < 16; c++){
        int co = co0 + c;
        float bv = bias[co];
        #pragma unroll
        for (int j = 0; j < 4; j++){
            size_t idx = ((size_t)(b*C+co))*L + l0 + lane + j*32;
            float att = sigmoid_f(acc[c][j] + bv);
            det[idx] = det[idx]*(1.0f + att);
        }
    }
}

// ---------------- host launch ----------------
extern "C" void kernel_launch(void* const* d_in, const int* in_sizes, int n_in,
                              void* d_out, int out_size)
{
    const float* x       = (const float*)d_in[0];
    const float* stat_w  = (const float*)d_in[1];
    const float* stat_b  = (const float*)d_in[2];
    const float* wg1_w   = (const float*)d_in[3];
    const float* wg1_b   = (const float*)d_in[4];
    const float* wg2_w   = (const float*)d_in[5];
    const float* wg2_b   = (const float*)d_in[6];
    const float* gates_w = (const float*)d_in[7];
    const float* gates_b = (const float*)d_in[8];
    const float* attn1_w = (const float*)d_in[9];
    const float* attn1_b = (const float*)d_in[10];
    const float* attn2_w = (const float*)d_in[11];
    const float* attn2_b = (const float*)d_in[12];
    float* out = (float*)d_out;

    float *a1, *a2, *a3, *attn, *feat, *wt;
    cudaGetSymbolAddress((void**)&a1,   g_a1);
    cudaGetSymbolAddress((void**)&a2,   g_a2);
    cudaGetSymbolAddress((void**)&a3,   g_a3);
    cudaGetSymbolAddress((void**)&attn, g_attn);
    cudaGetSymbolAddress((void**)&feat, g_feat);
    cudaGetSymbolAddress((void**)&wt,   g_wt);

    float* yl  = out;
    float* yh0 = out + NYL;
    float* yh1 = out + 2*NYL;
    float* yh2 = out + 3*NYL;
    float* scal= out + 4*NYL;            // [ortho, energy]
    float* lo_all = out + 4*NYL + 2;     // (3,B,9)
    float* hi_all = lo_all + 3*B*FL;

    // pre-transpose gates weights (all 3 levels)
    transpose_w_kernel<<<(3*C*C*3 + 255)/256, 256>>>(gates_w, wt);

    const float* ain[3]  = {x, a1, a2};
    float*       aout[3] = {a1, a2, a3};
    float*       dets[3] = {yh0, yh1, yh2};

    for (int lvl = 0; lvl < 3; lvl++){
        float* lo = lo_all + lvl*B*FL;
        float* hi = hi_all + lvl*B*FL;
        mean_kernel<<<NROW, 256>>>(ain[lvl], feat);
        mlp_kernel<<<B, 512>>>(feat, stat_w, stat_b, wg1_w, wg1_b, wg2_w, wg2_b, lo, hi);
        dw_kernel<<<dim3(L/DTL, NROW), 256>>>(ain[lvl], lo, hi, aout[lvl], dets[lvl]);
    }

    ortho_kernel<<<1, 32>>>(lo_all + 2*B*FL, scal);

    // reconstruction: i = 2 (no attn)
    gates_kernel<<<dim3(L/64, B), 256>>>(a3, yh2, wt + 2*C*3*C, gates_b + 2*C, a1);
    // i = 1
    attn1_kernel<<<dim3(L/128, B), 256>>>(a1, attn1_w + 1*(C/4)*C, attn1_b + (C/4), attn);
    attn2_kernel<<<dim3(L/128, B), 256>>>(attn, attn2_w + 1*C*(C/4), attn2_b + C, yh1);
    gates_kernel<<<dim3(L/64, B), 256>>>(a1, yh1, wt + 1*C*3*C, gates_b + 1*C, a2);
    // i = 0
    attn1_kernel<<<dim3(L/128, B), 256>>>(a2, attn1_w, attn1_b, attn);
    attn2_kernel<<<dim3(L/128, B), 256>>>(attn, attn2_w, attn2_b, yh0);
    gates_kernel<<<dim3(L/64, B), 256>>>(a2, yh0, wt, gates_b, yl);
}

// round 3
// speedup vs baseline: 1.7197x; 1.7197x over previous
#include <cuda_runtime.h>
#include <math.h>

#define B 32
#define C 128
#define L 4096
#define NROW (B*C)
#define BCL (B*C*L)            // 16777216
#define FL 9
#define DIM 512
#define NYL ((size_t)BCL)

// ---------------- scratch (device globals; no allocation) ----------------
__device__ float g_a1[BCL];
__device__ float g_a2[BCL];
__device__ float g_a3[BCL];
__device__ float g_attn[B*(C/4)*L];
__device__ float g_feat[B*C];
__device__ float g_wt[3*C*3*C];      // [lvl][ci][k][co]

__device__ __forceinline__ float gelu_f(float x){
    return 0.5f*x*(1.0f+erff(x*0.7071067811865476f));
}
__device__ __forceinline__ float sigmoid_f(float x){
    return 1.0f/(1.0f+expf(-x));
}

// ---- packed f32x2 helpers (Blackwell FFMA2) ----
__device__ __forceinline__ unsigned long long pack2(float lo, float hi){
    unsigned long long r;
    asm("mov.b64 %0, {%1, %2};" : "=l"(r) : "f"(lo), "f"(hi));
    return r;
}
__device__ __forceinline__ unsigned long long fma2(unsigned long long a, unsigned long long b, unsigned long long c){
    unsigned long long d;
    asm("fma.rn.f32x2 %0, %1, %2, %3;" : "=l"(d) : "l"(a), "l"(b), "l"(c));
    return d;
}
__device__ __forceinline__ float2 unpack2(unsigned long long v){
    float2 f;
    asm("mov.b64 {%0, %1}, %2;" : "=f"(f.x), "=f"(f.y) : "l"(v));
    return f;
}

// ---------------- mean over L ----------------
__global__ __launch_bounds__(256) void mean_kernel(const float* __restrict__ x,
                                                   float* __restrict__ feat){
    int row = blockIdx.x;
    const float4* p = (const float4*)(x + (size_t)row*L);
    float s = 0.f;
    for (int i = threadIdx.x; i < L/4; i += 256){
        float4 v = p[i];
        s += (v.x+v.y)+(v.z+v.w);
    }
    __shared__ float red[256];
    red[threadIdx.x] = s; __syncthreads();
    for (int off = 128; off > 0; off >>= 1){
        if (threadIdx.x < off) red[threadIdx.x] += red[threadIdx.x+off];
        __syncthreads();
    }
    if (threadIdx.x == 0) feat[row] = red[0] * (1.0f/(float)L);
}

// ---------------- fused MLP: feat->512->1024->18, write lo/hi ----------------
__global__ __launch_bounds__(512) void mlp_kernel(
    const float* __restrict__ feat,
    const float* __restrict__ stat_w, const float* __restrict__ stat_b,
    const float* __restrict__ wg1_w,  const float* __restrict__ wg1_b,
    const float* __restrict__ wg2_w,  const float* __restrict__ wg2_b,
    float* __restrict__ lo_out, float* __restrict__ hi_out)
{
    __shared__ float s_feat[C];
    __shared__ float s_h1[DIM];
    __shared__ float s_h2[2*DIM];
    int b = blockIdx.x, t = threadIdx.x;
    if (t < C) s_feat[t] = feat[b*C + t];
    __syncthreads();
    // layer 1: 512 outputs, K=128
    {
        float acc = stat_b[t];
        const float4* wr = (const float4*)(stat_w + (size_t)t*C);
        #pragma unroll 8
        for (int c = 0; c < C/4; c++){
            float4 w4 = wr[c];
            acc += w4.x*s_feat[4*c] + w4.y*s_feat[4*c+1] + w4.z*s_feat[4*c+2] + w4.w*s_feat[4*c+3];
        }
        s_h1[t] = gelu_f(acc);
    }
    __syncthreads();
    // layer 2: 1024 outputs, K=512
    #pragma unroll
    for (int rep = 0; rep < 2; rep++){
        int j = t + rep*DIM;
        float acc = wg1_b[j];
        const float4* wr = (const float4*)(wg1_w + (size_t)j*DIM);
        #pragma unroll 8
        for (int c = 0; c < DIM/4; c++){
            float4 w4 = wr[c];
            acc += w4.x*s_h1[4*c] + w4.y*s_h1[4*c+1] + w4.z*s_h1[4*c+2] + w4.w*s_h1[4*c+3];
        }
        s_h2[j] = gelu_f(acc);
    }
    __syncthreads();
    // layer 3: 18 outputs, K=1024
    if (t < 2*FL){
        float acc = wg2_b[t];
        const float4* wr = (const float4*)(wg2_w + (size_t)t*(2*DIM));
        #pragma unroll 8
        for (int c = 0; c < 2*DIM/4; c++){
            float4 w4 = wr[c];
            acc += w4.x*s_h2[4*c] + w4.y*s_h2[4*c+1] + w4.z*s_h2[4*c+2] + w4.w*s_h2[4*c+3];
        }
        if (t < FL) lo_out[b*FL + t]        = acc;
        else        hi_out[b*FL + (t-FL)]   = acc;
    }
}

// ---------------- ortho loss (last level only) + energy=0 ----------------
__global__ void ortho_kernel(const float* __restrict__ lo, float* __restrict__ out_scalars){
    int b = threadIdx.x;  // 32 threads
    float v[FL]; float ss = 0.f;
    #pragma unroll
    for (int k = 0; k < FL; k++){ v[k] = lo[b*FL+k]; ss += v[k]*v[k]; }
    float den = sqrtf(ss) + 1e-8f;
    float S = 0.f, sq = 0.f;
    #pragma unroll
    for (int k = 0; k < FL; k++){
        float n = v[k]/den;
        S  += fabsf(n);
        sq += n*n;
    }
    float S2  = S*S;
    float amp = fabsf(sq - 1.0f);
    float sm  = fabsf(v[0]);
    #pragma unroll
    for (int k = 1; k < FL; k++) sm += fabsf(v[k]-v[k-1]);
    sm += fabsf(v[FL-1]);
    #pragma unroll
    for (int off = 16; off > 0; off >>= 1){
        S2  += __shfl_xor_sync(0xffffffffu, S2,  off);
        amp += __shfl_xor_sync(0xffffffffu, amp, off);
        sm  += __shfl_xor_sync(0xffffffffu, sm,  off);
    }
    if (b == 0){
        float shift  = 3.0f * S2 / (32.0f*81.0f);
        float ampm   = amp / 32.0f;
        float smm    = sm / (32.0f*10.0f);
        out_scalars[0] = 0.01f*(shift + ampm) + 0.1f*smm;  // ortho_loss
        out_scalars[1] = 0.0f;                              // energy_loss
    }
}

// ---------------- per-sample depthwise 9-tap (edge pad), lo+hi fused, vectorized ----------------
#define DTL 1024
__global__ __launch_bounds__(256) void dw_kernel(
    const float* __restrict__ x, const float* __restrict__ lo, const float* __restrict__ hi,
    float* __restrict__ out_a, float* __restrict__ out_d)
{
    int row = blockIdx.y;          // b*C + c
    int b   = row >> 7;
    int l0  = blockIdx.x * DTL;
    __shared__ __align__(16) float s[DTL + 16];   // s[j] = x[l0 + j - 4], j in [0, DTL+8)
    const float* xr = x + (size_t)row * L;
    int t = threadIdx.x;
    // interior (aligned): s[4 .. 4+DTL) = x[l0 .. l0+DTL)
    {
        const float4* xv = (const float4*)(xr + l0);
        ((float4*)(s + 4))[t] = xv[t];
    }
    // edges
    if (t < 4){
        int li = l0 - 4 + t;
        s[t] = xr[max(li, 0)];
        int ri = l0 + DTL + t;
        s[DTL + 4 + t] = xr[min(ri, L-1)];
    }
    // filters packed (lo,hi)
    unsigned long long pf[FL];
    #pragma unroll
    for (int k = 0; k < FL; k++) pf[k] = pack2(__ldg(&lo[b*FL+k]), __ldg(&hi[b*FL+k]));
    __syncthreads();

    int i0 = t * 4;
    float win[12];
    #pragma unroll
    for (int j = 0; j < 12; j++) win[j] = s[i0 + j];
    unsigned long long acc[4];
    #pragma unroll
    for (int p = 0; p < 4; p++) acc[p] = 0ull;
    #pragma unroll
    for (int k = 0; k < FL; k++){
        #pragma unroll
        for (int p = 0; p < 4; p++){
            unsigned long long vv = pack2(win[p+k], win[p+k]);
            acc[p] = fma2(vv, pf[k], acc[p]);
        }
    }
    float4 ra, rd;
    float2 f0 = unpack2(acc[0]), f1 = unpack2(acc[1]), f2 = unpack2(acc[2]), f3 = unpack2(acc[3]);
    ra.x = f0.x; ra.y = f1.x; ra.z = f2.x; ra.w = f3.x;
    rd.x = f0.y; rd.y = f1.y; rd.z = f2.y; rd.w = f3.y;
    size_t idx = (size_t)row*L + l0 + i0;
    *(float4*)(out_a + idx) = ra;
    *(float4*)(out_d + idx) = rd;
}

// ---------------- transpose gates weights: [lvl][co][ci][k] -> [lvl][ci][k][co] ----------------
__global__ void transpose_w_kernel(const float* __restrict__ gw, float* __restrict__ wt){
    int idx = blockIdx.x*256 + threadIdx.x;
    if (idx < 3*C*C*3){
        int lvl = idx / (C*C*3);
        int r   = idx % (C*C*3);
        int ci  = r / (3*C);
        int k   = (r % (3*C)) / C;
        int co  = r % C;
        wt[idx] = gw[(size_t)lvl*C*C*3 + ((size_t)co*C + ci)*3 + k];
    }
}

// ---------------- gates conv: out = cur + sigmoid(conv3(cur)) * det (FFMA2) ----------------
// grid (L/64, B), 256 threads; warp w -> co[16w..16w+15] as 8 pairs, lane -> l in {lane, lane+32}
__global__ __launch_bounds__(256) void gates_kernel(
    const float* __restrict__ cur, const float* __restrict__ det,
    const float* __restrict__ wt /* [ci][k][co] */, const float* __restrict__ bias,
    float* __restrict__ out)
{
    __shared__ __align__(16) float s_x[C*66];       // [ci][j], window l0-1 .. l0+64
    __shared__ __align__(16) float s_w[8*3*C];      // ci chunk of 8
    int l0 = blockIdx.x*64, b = blockIdx.y, t = threadIdx.x;
    for (int idx = t; idx < C*66; idx += 256){
        int ci = idx/66, j = idx%66;
        int li = l0 + j - 1;
        float v = 0.f;
        if (li >= 0 && li < L) v = cur[((size_t)(b*C+ci))*L + li];
        s_x[idx] = v;
    }
    int wid = t >> 5, lane = t & 31, co0 = wid*16;
    unsigned long long acc[8][2];   // co pairs (co0+2c, co0+2c+1) x l in {lane, lane+32}
    #pragma unroll
    for (int c = 0; c < 8; c++){ acc[c][0] = 0ull; acc[c][1] = 0ull; }

    for (int ci0 = 0; ci0 < C; ci0 += 8){
        __syncthreads();
        for (int idx = t; idx < 8*3*C; idx += 256) s_w[idx] = wt[ci0*3*C + idx];
        __syncthreads();
        #pragma unroll
        for (int ci = 0; ci < 8; ci++){
            #pragma unroll
            for (int k = 0; k < 3; k++){
                const ulonglong2* wp = (const ulonglong2*)(&s_w[(ci*3+k)*C + co0]);
                unsigned long long wr[8];
                ((ulonglong2*)wr)[0] = wp[0];
                ((ulonglong2*)wr)[1] = wp[1];
                ((ulonglong2*)wr)[2] = wp[2];
                ((ulonglong2*)wr)[3] = wp[3];
                float x0 = s_x[(ci0+ci)*66 + lane + k];
                float x1 = s_x[(ci0+ci)*66 + lane + 32 + k];
                unsigned long long p0 = pack2(x0, x0);
                unsigned long long p1 = pack2(x1, x1);
                #pragma unroll
                for (int c = 0; c < 8; c++){
                    acc[c][0] = fma2(wr[c], p0, acc[c][0]);
                    acc[c][1] = fma2(wr[c], p1, acc[c][1]);
                }
            }
        }
    }
    #pragma unroll
    for (int c = 0; c < 8; c++){
        int co = co0 + 2*c;
        float b0 = bias[co], b1 = bias[co+1];
        #pragma unroll
        for (int j = 0; j < 2; j++){
            float2 f = unpack2(acc[c][j]);
            size_t idx0 = ((size_t)(b*C+co))*L + l0 + lane + j*32;
            size_t idx1 = idx0 + L;
            float g0 = sigmoid_f(f.x + b0);
            float g1 = sigmoid_f(f.y + b1);
            out[idx0] = cur[idx0] + g0*det[idx0];
            out[idx1] = cur[idx1] + g1*det[idx1];
        }
    }
}

// ---------------- attn1: 1x1 conv 128->32 + gelu (FFMA2) ----------------
// grid (L/128, B), 256 threads; warp w -> co[4w..4w+3] as 2 pairs, lane -> l in lane+{0,32,64,96}
__global__ __launch_bounds__(256) void attn1_kernel(
    const float* __restrict__ cur, const float* __restrict__ w /* (32,128) */,
    const float* __restrict__ bias, float* __restrict__ outa)
{
    __shared__ __align__(16) float s_x[32*128];     // ci chunk of 32
    __shared__ __align__(16) float s_w[128*32];     // [ci][co], stride 32 (broadcast reads)
    int b = blockIdx.y, l0 = blockIdx.x*128, t = threadIdx.x;
    for (int idx = t; idx < C*32; idx += 256){
        int ci = idx >> 5, co = idx & 31;               // consecutive t -> co consecutive -> conflict-free store
        s_w[idx] = w[co*C + ci];
    }
    int wid = t >> 5, lane = t & 31, co0 = wid*4;
    unsigned long long acc[2][4];
    #pragma unroll
    for (int c = 0; c < 2; c++)
        #pragma unroll
        for (int j = 0; j < 4; j++) acc[c][j] = 0ull;

    for (int ci0 = 0; ci0 < C; ci0 += 32){
        __syncthreads();
        for (int idx = t; idx < 32*128; idx += 256){
            int ci = idx >> 7, l = idx & 127;
            s_x[idx] = cur[((size_t)(b*C + ci0 + ci))*L + l0 + l];
        }
        __syncthreads();
        #pragma unroll 4
        for (int ci = 0; ci < 32; ci++){
            unsigned long long wr[2];
            wr[0] = *(const unsigned long long*)(&s_w[(ci0+ci)*32 + co0]);
            wr[1] = *(const unsigned long long*)(&s_w[(ci0+ci)*32 + co0 + 2]);
            #pragma unroll
            for (int j = 0; j < 4; j++){
                float xv = s_x[ci*128 + lane + j*32];
                unsigned long long p = pack2(xv, xv);
                acc[0][j] = fma2(wr[0], p, acc[0][j]);
                acc[1][j] = fma2(wr[1], p, acc[1][j]);
            }
        }
    }
    #pragma unroll
    for (int c = 0; c < 2; c++){
        int co = co0 + 2*c;
        float b0 = bias[co], b1 = bias[co+1];
        #pragma unroll
        for (int j = 0; j < 4; j++){
            float2 f = unpack2(acc[c][j]);
            size_t idx0 = ((size_t)(b*32 + co))*L + l0 + lane + j*32;
            outa[idx0]     = gelu_f(f.x + b0);
            outa[idx0 + L] = gelu_f(f.y + b1);
        }
    }
}

// ---------------- attn2: 1x1 conv 32->128 + sigmoid; det *= (1+attn) in place (FFMA2) ----------------
// grid (L/128, B), 256 threads; warp w -> co[16w..16w+15] as 8 pairs, lane -> l in lane+{0,32,64,96}
__global__ __launch_bounds__(256) void attn2_kernel(
    const float* __restrict__ a, const float* __restrict__ w /* (128,32) */,
    const float* __restrict__ bias, float* __restrict__ det)
{
    __shared__ __align__(16) float s_x[32*128];
    __shared__ __align__(16) float s_w[32*132];     // [ci][co] padded stride 132
    int b = blockIdx.y, l0 = blockIdx.x*128, t = threadIdx.x;
    for (int idx = t; idx < 32*128; idx += 256){
        int ci = idx >> 7, l = idx & 127;
        s_x[idx] = a[((size_t)(b*32 + ci))*L + l0 + l];
    }
    for (int idx = t; idx < C*32; idx += 256){
        int ci = idx >> 7, co = idx & 127;              // consecutive t -> co consecutive -> conflict-free store
        s_w[ci*132 + co] = w[co*32 + ci];
    }
    __syncthreads();
    int wid = t >> 5, lane = t & 31, co0 = wid*16;
    unsigned long long acc[8][4];
    #pragma unroll
    for (int c = 0; c < 8; c++)
        #pragma unroll
        for (int j = 0; j < 4; j++) acc[c][j] = 0ull;
    #pragma unroll 2
    for (int ci = 0; ci < 32; ci++){
        unsigned long long wr[8];
        const ulonglong2* wp = (const ulonglong2*)(&s_w[ci*132 + co0]);
        ((ulonglong2*)wr)[0] = wp[0];
        ((ulonglong2*)wr)[1] = wp[1];
        ((ulonglong2*)wr)[2] = wp[2];
        ((ulonglong2*)wr)[3] = wp[3];
        #pragma unroll
        for (int j = 0; j < 4; j++){
            float xv = s_x[ci*128 + lane + j*32];
            unsigned long long p = pack2(xv, xv);
            #pragma unroll
            for (int c = 0; c < 8; c++)
                acc[c][j] = fma2(wr[c], p, acc[c][j]);
        }
    }
    #pragma unroll
    for (int c = 0; c < 8; c++){
        int co = co0 + 2*c;
        float b0 = bias[co], b1 = bias[co+1];
        #pragma unroll
        for (int j = 0; j < 4; j++){
            float2 f = unpack2(acc[c][j]);
            size_t idx0 = ((size_t)(b*C+co))*L + l0 + lane + j*32;
            size_t idx1 = idx0 + L;
            det[idx0] = det[idx0]*(1.0f + sigmoid_f(f.x + b0));
            det[idx1] = det[idx1]*(1.0f + sigmoid_f(f.y + b1));
        }
    }
}

// ---------------- host launch ----------------
extern "C" void kernel_launch(void* const* d_in, const int* in_sizes, int n_in,
                              void* d_out, int out_size)
{
    const float* x       = (const float*)d_in[0];
    const float* stat_w  = (const float*)d_in[1];
    const float* stat_b  = (const float*)d_in[2];
    const float* wg1_w   = (const float*)d_in[3];
    const float* wg1_b   = (const float*)d_in[4];
    const float* wg2_w   = (const float*)d_in[5];
    const float* wg2_b   = (const float*)d_in[6];
    const float* gates_w = (const float*)d_in[7];
    const float* gates_b = (const float*)d_in[8];
    const float* attn1_w = (const float*)d_in[9];
    const float* attn1_b = (const float*)d_in[10];
    const float* attn2_w = (const float*)d_in[11];
    const float* attn2_b = (const float*)d_in[12];
    float* out = (float*)d_out;

    float *a1, *a2, *a3, *attn, *feat, *wt;
    cudaGetSymbolAddress((void**)&a1,   g_a1);
    cudaGetSymbolAddress((void**)&a2,   g_a2);
    cudaGetSymbolAddress((void**)&a3,   g_a3);
    cudaGetSymbolAddress((void**)&attn, g_attn);
    cudaGetSymbolAddress((void**)&feat, g_feat);
    cudaGetSymbolAddress((void**)&wt,   g_wt);

    float* yl  = out;
    float* yh0 = out + NYL;
    float* yh1 = out + 2*NYL;
    float* yh2 = out + 3*NYL;
    float* scal= out + 4*NYL;            // [ortho, energy]
    float* lo_all = out + 4*NYL + 2;     // (3,B,9)
    float* hi_all = lo_all + 3*B*FL;

    // pre-transpose gates weights (all 3 levels)
    transpose_w_kernel<<<(3*C*C*3 + 255)/256, 256>>>(gates_w, wt);

    const float* ain[3]  = {x, a1, a2};
    float*       aout[3] = {a1, a2, a3};
    float*       dets[3] = {yh0, yh1, yh2};

    for (int lvl = 0; lvl < 3; lvl++){
        float* lo = lo_all + lvl*B*FL;
        float* hi = hi_all + lvl*B*FL;
        mean_kernel<<<NROW, 256>>>(ain[lvl], feat);
        mlp_kernel<<<B, 512>>>(feat, stat_w, stat_b, wg1_w, wg1_b, wg2_w, wg2_b, lo, hi);
        dw_kernel<<<dim3(L/DTL, NROW), 256>>>(ain[lvl], lo, hi, aout[lvl], dets[lvl]);
    }

    ortho_kernel<<<1, 32>>>(lo_all + 2*B*FL, scal);

    // reconstruction: i = 2 (no attn)
    gates_kernel<<<dim3(L/64, B), 256>>>(a3, yh2, wt + 2*C*3*C, gates_b + 2*C, a1);
    // i = 1
    attn1_kernel<<<dim3(L/128, B), 256>>>(a1, attn1_w + 1*(C/4)*C, attn1_b + (C/4), attn);
    attn2_kernel<<<dim3(L/128, B), 256>>>(attn, attn2_w + 1*C*(C/4), attn2_b + C, yh1);
    gates_kernel<<<dim3(L/64, B), 256>>>(a1, yh1, wt + 1*C*3*C, gates_b + 1*C, a2);
    // i = 0
    attn1_kernel<<<dim3(L/128, B), 256>>>(a2, attn1_w, attn1_b, attn);
    attn2_kernel<<<dim3(L/128, B), 256>>>(attn, attn2_w, attn2_b, yh0);
    gates_kernel<<<dim3(L/64, B), 256>>>(a2, yh0, wt, gates_b, yl);
}